// round 4
// baseline (speedup 1.0000x reference)
#include <cuda_runtime.h>
#include <cuda_bf16.h>
#include <math.h>
#include <cstdint>
#include <cstring>

// ---------------- problem constants ----------------
#define L       2048
#define BATCH   2
#define DM      768
#define DI      1536          // d_inner
#define DS      128           // d_state
#define HD      64            // headdim
#define NH      24            // heads
#define CONVD   1792          // conv_dim = DI + 2*DS
#define NPROJ   3352          // 2*DI + 2*DS + NH
#define NPAD    3456          // NPROJ padded to 27*128
#define M4      4096          // BATCH * L tokens per direction

// ---------------- scratch ----------------
__device__ float g_zx [2u * M4 * NPROJ];
__device__ float g_xBC[2u * M4 * CONVD];
__device__ float g_dt [2u * M4 * NH];
__device__ float g_dA [2u * M4 * NH];
__device__ float g_y  [2u * M4 * DI];

// split-bf16 operand arrays (hi / lo)
__device__ __nv_bfloat16 g_Ah0[2u * M4 * DM],   g_Al0[2u * M4 * DM];    // x, dir-flipped
__device__ __nv_bfloat16 g_Wh0[2u * NPAD * DM], g_Wl0[2u * NPAD * DM];  // in_w, zero-padded
__device__ __nv_bfloat16 g_Ah1[2u * M4 * DI],   g_Al1[2u * M4 * DI];    // normed y, dir-flipped
__device__ __nv_bfloat16 g_Wh1[2u * DM * DI],   g_Wl1[2u * DM * DI];    // out_w

// =====================================================================
// helpers
// =====================================================================
__device__ __forceinline__ uint32_t smem_u32(const void* p) {
    uint32_t a;
    asm("{ .reg .u64 t; cvta.to.shared.u64 t, %1; cvt.u32.u64 %0, t; }" : "=r"(a) : "l"(p));
    return a;
}
__device__ __forceinline__ uint32_t b2u(__nv_bfloat162 v) {
    uint32_t u; memcpy(&u, &v, 4); return u;
}
__device__ __forceinline__ void ldsm4(uint32_t& r0, uint32_t& r1, uint32_t& r2, uint32_t& r3,
                                      uint32_t addr) {
    asm volatile("ldmatrix.sync.aligned.m8n8.x4.shared.b16 {%0,%1,%2,%3}, [%4];"
        : "=r"(r0), "=r"(r1), "=r"(r2), "=r"(r3) : "r"(addr));
}
__device__ __forceinline__ void mma16816(float* c, const uint32_t* a, const uint32_t* b) {
    asm volatile(
        "mma.sync.aligned.m16n8k16.row.col.f32.bf16.bf16.f32 "
        "{%0,%1,%2,%3}, {%4,%5,%6,%7}, {%8,%9}, {%0,%1,%2,%3};"
        : "+f"(c[0]), "+f"(c[1]), "+f"(c[2]), "+f"(c[3])
        : "r"(a[0]), "r"(a[1]), "r"(a[2]), "r"(a[3]), "r"(b[0]), "r"(b[1]));
}
__device__ __forceinline__ void cpa16(uint32_t dst, const void* src) {
    asm volatile("cp.async.cg.shared.global [%0], [%1], 16;" :: "r"(dst), "l"(src));
}
// split float4 into packed bf16 hi / lo (2x bf162 each)
__device__ __forceinline__ void split4(float4 v, uint2& h, uint2& l) {
    __nv_bfloat162 h0 = __float22bfloat162_rn(make_float2(v.x, v.y));
    __nv_bfloat162 h1 = __float22bfloat162_rn(make_float2(v.z, v.w));
    float2 f0 = __bfloat1622float2(h0), f1 = __bfloat1622float2(h1);
    __nv_bfloat162 l0 = __float22bfloat162_rn(make_float2(v.x - f0.x, v.y - f0.y));
    __nv_bfloat162 l1 = __float22bfloat162_rn(make_float2(v.z - f1.x, v.w - f1.y));
    h = make_uint2(b2u(h0), b2u(h1));
    l = make_uint2(b2u(l0), b2u(l1));
}

// =====================================================================
// operand split kernels
// =====================================================================
__global__ void __launch_bounds__(256) split_x(const float* __restrict__ x)
{
    const int idx = blockIdx.x * 256 + threadIdx.x;   // over 2*M4*(DM/4)
    if (idx >= 2 * M4 * (DM / 4)) return;
    const int k4 = idx % (DM / 4);
    const int rm = idx / (DM / 4);                    // dir*M4 + m
    const int m  = rm & (M4 - 1);
    const int dir = rm >> 12;
    const int t = m & (L - 1), st = dir ? (L - 1 - t) : t;
    const float4 v = *(const float4*)(x + ((size_t)((m >> 11) * L + st)) * DM + k4 * 4);
    uint2 h, l; split4(v, h, l);
    *(uint2*)(g_Ah0 + (size_t)rm * DM + k4 * 4) = h;
    *(uint2*)(g_Al0 + (size_t)rm * DM + k4 * 4) = l;
}

__global__ void __launch_bounds__(256) split_w0(const float* __restrict__ w)
{
    const int idx = blockIdx.x * 256 + threadIdx.x;   // over 2*NPAD*(DM/4)
    if (idx >= 2 * NPAD * (DM / 4)) return;
    const int k4 = idx % (DM / 4);
    const int rn = idx / (DM / 4);                    // dir*NPAD + n
    const int n  = rn % NPAD;
    const int dir = rn / NPAD;
    float4 v = make_float4(0.f, 0.f, 0.f, 0.f);
    if (n < NPROJ)
        v = *(const float4*)(w + ((size_t)dir * NPROJ + n) * DM + k4 * 4);
    uint2 h, l; split4(v, h, l);
    *(uint2*)(g_Wh0 + (size_t)rn * DM + k4 * 4) = h;
    *(uint2*)(g_Wl0 + (size_t)rn * DM + k4 * 4) = l;
}

__global__ void __launch_bounds__(256) split_w1(const float* __restrict__ w)
{
    const int idx = blockIdx.x * 256 + threadIdx.x;   // over 2*DM*(DI/4), linear
    if (idx >= 2 * DM * (DI / 4)) return;
    const float4 v = *(const float4*)(w + (size_t)idx * 4);
    uint2 h, l; split4(v, h, l);
    *(uint2*)(g_Wh1 + (size_t)idx * 4) = h;
    *(uint2*)(g_Wl1 + (size_t)idx * 4) = l;
}

// =====================================================================
// bf16 split GEMM, cp.async 3-stage pipeline.
//   C[m][n] = sum_k A[m][k]*B[n][k], 3 products (hh + hl + lh).
//   MODE 0: in_proj  (K=768, grid 27x32x2, writes g_zx fp32 guarded)
//   MODE 1: out_proj (K=2x1536 over dirs, grid 6x32x1, writes out)
// Block 128x128x32, 8 warps (2x4), warp tile 64x32.
// smem per stage: 4 arrays x 128 rows x 80B = 40960B; 3 stages = 120KB.
// =====================================================================
#define STAGE_BYTES 40960
#define ARR_BYTES   10240
#define GEMM_SMEM   (3 * STAGE_BYTES)

template <int MODE>
__global__ void __launch_bounds__(256) mma_gemm(float* __restrict__ Cg)
{
    extern __shared__ __align__(128) char smem[];
    const uint32_t sb = smem_u32(smem);

    const int tid  = threadIdx.x;
    const int wid  = tid >> 5;
    const int lane = tid & 31;
    const int n0   = blockIdx.x * 128;
    const int m0   = blockIdx.y * 128;
    const int dir0 = blockIdx.z;

    const int KDIM = (MODE == 0) ? DM : DI;
    const int S    = (MODE == 0) ? (DM / 32) : (2 * (DI / 32));   // 24 or 96

    // ---- loader mapping: arr = which operand, 2 rows x 4 chunks of 16B ----
    const int arr = tid >> 6;            // 0 Ah, 1 Al, 2 Wh, 3 Wl
    const int rw0 = (tid & 63) * 2;
    const uint32_t sdst0 = sb + arr * ARR_BYTES + rw0 * 80;

    const __nv_bfloat16* srcp[2];
    if (MODE == 0) {
        const __nv_bfloat16* base = (arr == 0) ? g_Ah0 : (arr == 1) ? g_Al0
                                  : (arr == 2) ? g_Wh0 : g_Wl0;
        const size_t rowi = (arr < 2) ? ((size_t)dir0 * M4 + m0 + rw0)
                                      : ((size_t)dir0 * NPAD + n0 + rw0);
        srcp[0] = base + rowi * DM;
        srcp[1] = srcp[0];
    } else {
        const __nv_bfloat16* base = (arr == 0) ? g_Ah1 : (arr == 1) ? g_Al1
                                  : (arr == 2) ? g_Wh1 : g_Wl1;
        const size_t r0 = (arr < 2) ? ((size_t)(m0 + rw0)) : ((size_t)(n0 + rw0));
        const size_t r1 = (arr < 2) ? ((size_t)M4 + m0 + rw0) : ((size_t)DM + n0 + rw0);
        srcp[0] = base + r0 * DI;
        srcp[1] = base + r1 * DI;
    }

#define ISSUE(s) do {                                                        \
        const int _s = (s);                                                  \
        int _d, _k0;                                                         \
        if (MODE == 0) { _d = 0; _k0 = _s * 32; }                            \
        else { _d = (_s >= 48); _k0 = (_s - _d * 48) * 32; }                 \
        const __nv_bfloat16* _p = srcp[_d] + _k0;                            \
        const uint32_t _dst = sdst0 + (_s % 3) * STAGE_BYTES;                \
        cpa16(_dst +  0, _p);                                                \
        cpa16(_dst + 16, _p + 8);                                            \
        cpa16(_dst + 32, _p + 16);                                           \
        cpa16(_dst + 48, _p + 24);                                           \
        cpa16(_dst + 80 +  0, _p + KDIM);                                    \
        cpa16(_dst + 80 + 16, _p + KDIM + 8);                                \
        cpa16(_dst + 80 + 32, _p + KDIM + 16);                               \
        cpa16(_dst + 80 + 48, _p + KDIM + 24);                               \
        asm volatile("cp.async.commit_group;" ::: "memory");                 \
    } while (0)

    float acc[4][4][4];
#pragma unroll
    for (int i = 0; i < 4; ++i)
#pragma unroll
        for (int j = 0; j < 4; ++j)
#pragma unroll
            for (int k = 0; k < 4; ++k) acc[i][j][k] = 0.f;

    const int wm  = (wid >> 2) * 64;
    const int wn  = (wid & 3) * 32;
    const int arl = (lane & 7) + ((lane >> 3) & 1) * 8;   // A ldmatrix row
    const int akb = (lane >> 4) * 16;                     // A ldmatrix k-byte
    const int brl = (lane & 7) + (lane >> 4) * 8;         // B ldmatrix row
    const int bkb = ((lane >> 3) & 1) * 16;               // B ldmatrix k-byte

    ISSUE(0);
    ISSUE(1);

    for (int s = 0; s < S; ++s) {
        if (s == S - 1) asm volatile("cp.async.wait_group 0;" ::: "memory");
        else            asm volatile("cp.async.wait_group 1;" ::: "memory");
        __syncthreads();
        if (s + 2 < S) ISSUE(s + 2);

        const uint32_t ub  = sb + (s % 3) * STAGE_BYTES;
        const uint32_t uAh = ub;
        const uint32_t uAl = ub + ARR_BYTES;
        const uint32_t uBh = ub + 2 * ARR_BYTES;
        const uint32_t uBl = ub + 3 * ARR_BYTES;

#pragma unroll
        for (int ks = 0; ks < 2; ++ks) {
            uint32_t ah[4][4], al_[4][4], bh[2][4], bl[2][4];
#pragma unroll
            for (int mf = 0; mf < 4; ++mf) {
                const uint32_t off = (uint32_t)(wm + mf * 16 + arl) * 80 + ks * 32 + akb;
                ldsm4(ah[mf][0],  ah[mf][1],  ah[mf][2],  ah[mf][3],  uAh + off);
                ldsm4(al_[mf][0], al_[mf][1], al_[mf][2], al_[mf][3], uAl + off);
            }
#pragma unroll
            for (int nf2 = 0; nf2 < 2; ++nf2) {
                const uint32_t off = (uint32_t)(wn + nf2 * 16 + brl) * 80 + ks * 32 + bkb;
                ldsm4(bh[nf2][0], bh[nf2][1], bh[nf2][2], bh[nf2][3], uBh + off);
                ldsm4(bl[nf2][0], bl[nf2][1], bl[nf2][2], bl[nf2][3], uBl + off);
            }
#pragma unroll
            for (int mf = 0; mf < 4; ++mf)
#pragma unroll
                for (int nf = 0; nf < 4; ++nf) {
                    const uint32_t* bhp = &bh[nf >> 1][(nf & 1) * 2];
                    const uint32_t* blp = &bl[nf >> 1][(nf & 1) * 2];
                    mma16816(acc[mf][nf], ah[mf],  bhp);
                    mma16816(acc[mf][nf], ah[mf],  blp);
                    mma16816(acc[mf][nf], al_[mf], bhp);
                }
        }
    }
#undef ISSUE

    // ---- epilogue ----
    const int g  = lane >> 2;
    const int tg = lane & 3;
#pragma unroll
    for (int mf = 0; mf < 4; ++mf)
#pragma unroll
        for (int nf = 0; nf < 4; ++nf) {
            const int mrow = m0 + wm + mf * 16 + g;
            const int ncol = n0 + wn + nf * 8 + tg * 2;
            const float* c = acc[mf][nf];
            if (MODE == 0) {
                if (ncol < NPROJ) {
                    float* o0 = g_zx + ((size_t)(dir0 * M4 + mrow)) * NPROJ + ncol;
                    float* o1 = g_zx + ((size_t)(dir0 * M4 + mrow + 8)) * NPROJ + ncol;
                    o0[0] = c[0]; o0[1] = c[1];
                    o1[0] = c[2]; o1[1] = c[3];
                }
            } else {
                float* o0 = Cg + (size_t)mrow * DM + ncol;
                float* o1 = Cg + (size_t)(mrow + 8) * DM + ncol;
                o0[0] = c[0]; o0[1] = c[1];
                o1[0] = c[2]; o1[1] = c[3];
            }
        }
}

// =====================================================================
// dt/dA precompute
// =====================================================================
__global__ void dtdA_kernel(const float* __restrict__ dt_bias,
                            const float* __restrict__ A_log)
{
    const int idx = blockIdx.x * 256 + threadIdx.x;
    if (idx >= 2 * M4 * NH) return;
    const int hh  = idx % NH;
    const int rm  = idx / NH;
    const int dir = rm >> 12;
    const float raw = g_zx[(size_t)rm * NPROJ + (DI + CONVD) + hh] + dt_bias[dir * NH + hh];
    const float dtv = (raw > 20.f) ? raw : log1pf(expf(raw));
    const float A   = -expf(A_log[dir * NH + hh]);
    g_dt[idx] = dtv;
    g_dA[idx] = expf(dtv * A);
}

// =====================================================================
// depthwise causal conv(4) + SiLU
// =====================================================================
__global__ void __launch_bounds__(256) conv_kernel(const float* __restrict__ conv_w,
                                                   const float* __restrict__ conv_b)
{
    const int db  = blockIdx.z;
    const int dir = db >> 1;
    const int b   = db & 1;
    const int t0  = blockIdx.y * 32;
    const int tid = threadIdx.x;

    __shared__ float s[35][256];

    for (int cbk = 0; cbk < CONVD; cbk += 256) {
        const int c = cbk + tid;
        __syncthreads();
#pragma unroll
        for (int rr = 0; rr < 35; ++rr) {
            const int tin = t0 - 3 + rr;
            float val = 0.f;
            if (tin >= 0)
                val = g_zx[((size_t)(dir * M4 + b * L + tin)) * NPROJ + DI + c];
            s[rr][tid] = val;
        }
        __syncthreads();
        const float w0 = conv_w[(dir * CONVD + c) * 4 + 0];
        const float w1 = conv_w[(dir * CONVD + c) * 4 + 1];
        const float w2 = conv_w[(dir * CONVD + c) * 4 + 2];
        const float w3 = conv_w[(dir * CONVD + c) * 4 + 3];
        const float bias = conv_b[dir * CONVD + c];
#pragma unroll 4
        for (int tt = 0; tt < 32; ++tt) {
            float v = bias;
            v = fmaf(s[tt + 0][tid], w0, v);
            v = fmaf(s[tt + 1][tid], w1, v);
            v = fmaf(s[tt + 2][tid], w2, v);
            v = fmaf(s[tt + 3][tid], w3, v);
            const float o = v / (1.f + expf(-v));
            g_xBC[((size_t)(dir * M4 + b * L + t0 + tt)) * CONVD + c] = o;
        }
    }
}

// =====================================================================
// selective scan (96 blocks, 128 threads, register-resident state)
// =====================================================================
__global__ void __launch_bounds__(128) scan_kernel(const float* __restrict__ Dvec)
{
    const int h   = blockIdx.x;
    const int b   = blockIdx.y;
    const int dir = blockIdx.z;
    const int tid = threadIdx.x;
    const int ni  = tid & 7;
    const int pi  = tid >> 3;

    __shared__ float sx[3][64];
    __shared__ float sB[3][128];
    __shared__ float sC[3][128];
    __shared__ float ss[3][2];

    const float Dval  = Dvec[dir * NH + h];
    const int rowbase = dir * M4 + b * L;

    float hreg[4][16];
#pragma unroll
    for (int pp = 0; pp < 4; ++pp)
#pragma unroll
        for (int nn = 0; nn < 16; ++nn) hreg[pp][nn] = 0.f;

    {
        const float* row = g_xBC + (size_t)rowbase * CONVD;
        if (tid < 64) sx[0][tid] = row[h * HD + tid];
        sB[0][tid] = row[DI + tid];
        sC[0][tid] = row[DI + DS + tid];
        if (tid == 0) {
            ss[0][0] = g_dt[rowbase * NH + h];
            ss[0][1] = g_dA[rowbase * NH + h];
        }
    }
    __syncthreads();

    int cur = 0;
    for (int t = 0; t < L; ++t) {
        float rx = 0.f, rb = 0.f, rc = 0.f, rdt = 0.f, rdA = 0.f;
        if (t + 1 < L) {
            const float* row = g_xBC + (size_t)(rowbase + t + 1) * CONVD;
            if (tid < 64) rx = row[h * HD + tid];
            rb = row[DI + tid];
            rc = row[DI + DS + tid];
            if (tid == 0) {
                rdt = g_dt[(rowbase + t + 1) * NH + h];
                rdA = g_dA[(rowbase + t + 1) * NH + h];
            }
        }

        const float dt = ss[cur][0];
        const float dA = ss[cur][1];
        float xv[4], coef[4], acc[4];
#pragma unroll
        for (int pp = 0; pp < 4; ++pp) {
            xv[pp]   = sx[cur][pi * 4 + pp];
            coef[pp] = dt * xv[pp];
            acc[pp]  = 0.f;
        }
#pragma unroll
        for (int nn = 0; nn < 16; ++nn) {
            const float Bv = sB[cur][ni * 16 + nn];
            const float Cv = sC[cur][ni * 16 + nn];
#pragma unroll
            for (int pp = 0; pp < 4; ++pp) {
                const float hv = fmaf(hreg[pp][nn], dA, coef[pp] * Bv);
                hreg[pp][nn] = hv;
                acc[pp] = fmaf(hv, Cv, acc[pp]);
            }
        }
#pragma unroll
        for (int pp = 0; pp < 4; ++pp) {
            acc[pp] += __shfl_xor_sync(0xffffffffu, acc[pp], 1);
            acc[pp] += __shfl_xor_sync(0xffffffffu, acc[pp], 2);
            acc[pp] += __shfl_xor_sync(0xffffffffu, acc[pp], 4);
        }
        if (ni == 0) {
            float* yp = g_y + (size_t)(rowbase + t) * DI + h * HD + pi * 4;
#pragma unroll
            for (int pp = 0; pp < 4; ++pp)
                yp[pp] = fmaf(Dval, xv[pp], acc[pp]);
        }

        const int nxt = (cur == 2) ? 0 : cur + 1;
        if (t + 1 < L) {
            if (tid < 64) sx[nxt][tid] = rx;
            sB[nxt][tid] = rb;
            sC[nxt][tid] = rc;
            if (tid == 0) { ss[nxt][0] = rdt; ss[nxt][1] = rdA; }
        }
        __syncthreads();
        cur = nxt;
    }
}

// =====================================================================
// gate + RMSNorm; emits split bf16 A-operand for out_proj (dir-flipped)
// =====================================================================
__global__ void __launch_bounds__(256) gatenorm_kernel(const float* __restrict__ norm_w)
{
    const int row = blockIdx.x;          // dir*M4 + m
    const int dir = row >> 12;
    const int m   = row & (M4 - 1);
    const int tid = threadIdx.x;
    const float* yrow = g_y + (size_t)row * DI;
    const float* zrow = g_zx + (size_t)row * NPROJ;

    float v[6];
    float ssum = 0.f;
#pragma unroll
    for (int i = 0; i < 6; ++i) {
        const int c = tid + i * 256;
        const float zv = zrow[c];
        const float val = yrow[c] * (zv / (1.f + expf(-zv)));
        v[i] = val;
        ssum += val * val;
    }
#pragma unroll
    for (int o = 16; o > 0; o >>= 1)
        ssum += __shfl_xor_sync(0xffffffffu, ssum, o);

    __shared__ float red[8];
    if ((tid & 31) == 0) red[tid >> 5] = ssum;
    __syncthreads();
    if (tid == 0) {
        float tot = 0.f;
#pragma unroll
        for (int i = 0; i < 8; ++i) tot += red[i];
        red[0] = rsqrtf(tot / (float)DI + 1e-5f);
    }
    __syncthreads();
    const float scale = red[0];

    // destination row: flip within batch for dir=1 so out_proj reads linearly
    const int t    = m & (L - 1);
    const int dstm = dir ? (m - t + (L - 1 - t)) : m;
    __nv_bfloat16* ah = g_Ah1 + ((size_t)dir * M4 + dstm) * DI;
    __nv_bfloat16* al = g_Al1 + ((size_t)dir * M4 + dstm) * DI;

#pragma unroll
    for (int i = 0; i < 6; ++i) {
        const int c = tid + i * 256;
        const float val = v[i] * scale * norm_w[dir * DI + c];
        const __nv_bfloat16 hb = __float2bfloat16(val);
        const float lf = val - __bfloat162float(hb);
        ah[c] = hb;
        al[c] = __float2bfloat16(lf);
    }
}

// =====================================================================
// launch
// =====================================================================
extern "C" void kernel_launch(void* const* d_in, const int* in_sizes, int n_in,
                              void* d_out, int out_size)
{
    (void)in_sizes; (void)n_in; (void)out_size;
    const float* x       = (const float*)d_in[0];
    const float* in_w    = (const float*)d_in[1];
    const float* conv_w  = (const float*)d_in[2];
    const float* conv_b  = (const float*)d_in[3];
    const float* dt_bias = (const float*)d_in[4];
    const float* A_log   = (const float*)d_in[5];
    const float* Dp      = (const float*)d_in[6];
    const float* norm_w  = (const float*)d_in[7];
    const float* out_w   = (const float*)d_in[8];
    float* out = (float*)d_out;

    static bool attr_set = false;
    cudaFuncSetAttribute(mma_gemm<0>, cudaFuncAttributeMaxDynamicSharedMemorySize, GEMM_SMEM);
    cudaFuncSetAttribute(mma_gemm<1>, cudaFuncAttributeMaxDynamicSharedMemorySize, GEMM_SMEM);
    (void)attr_set;

    split_x <<<(2 * M4 * (DM / 4) + 255) / 256, 256>>>(x);
    split_w0<<<(2 * NPAD * (DM / 4) + 255) / 256, 256>>>(in_w);
    split_w1<<<(2 * DM * (DI / 4) + 255) / 256, 256>>>(out_w);

    mma_gemm<0><<<dim3(NPAD / 128, M4 / 128, 2), 256, GEMM_SMEM>>>(nullptr);
    dtdA_kernel<<<(2 * M4 * NH + 255) / 256, 256>>>(dt_bias, A_log);
    conv_kernel<<<dim3(1, L / 32, 4), 256>>>(conv_w, conv_b);
    scan_kernel<<<dim3(NH, BATCH, 2), 128>>>(Dp);
    gatenorm_kernel<<<2 * M4, 256>>>(norm_w);
    mma_gemm<1><<<dim3(DM / 128, M4 / 128, 1), 256, GEMM_SMEM>>>(out);
}